// round 1
// baseline (speedup 1.0000x reference)
#include <cuda_runtime.h>
#include <cstddef>

#define NN  102400
#define DD  128
#define LL  5
#define TSG 1024

// ---------------- scratch (static device globals; no allocation) -------------
__device__ float g_h[(size_t)NN * DD];        // 52.4 MB
__device__ float g_agg[(size_t)NN * DD];      // 52.4 MB
__device__ float g_y[(size_t)NN * 2 * DD];    // 104.8 MB
__device__ float g_cnt[TSG];
__device__ int   g_off[1024];

// ---------------- graph-offset prefix (tiny, G=64) ---------------------------
__global__ void prefix_kernel(const int* __restrict__ ns, int G) {
    if (blockIdx.x == 0 && threadIdx.x == 0) {
        int a = 0;
        for (int g = 0; g < G; ++g) { g_off[g] = a; a += ns[g]; }
    }
}

// ---------------- agg = (1+eps_l) * h ----------------------------------------
__global__ void init_agg_kernel(const float* __restrict__ h,
                                const float* __restrict__ eps, int l,
                                int total4) {
    int i = blockIdx.x * blockDim.x + threadIdx.x;
    if (i >= total4) return;
    float e = 1.0f + eps[l];
    float4 v = ((const float4*)h)[i];
    v.x *= e; v.y *= e; v.z *= e; v.w *= e;
    ((float4*)g_agg)[i] = v;
}

// ---------------- warp-per-edge scatter: agg[dst] += h[src] ------------------
__global__ void scatter_kernel(const float* __restrict__ h,
                               const int* __restrict__ src,
                               const int* __restrict__ dst, int E) {
    long long tid = (long long)blockIdx.x * blockDim.x + threadIdx.x;
    int e = (int)(tid >> 5);
    if (e >= E) return;
    int lane = (int)(tid & 31);
    int s = src[e], d = dst[e];
    float4 v = ((const float4*)(h + (size_t)s * DD))[lane];
    float* a = g_agg + (size_t)d * DD + lane * 4;
    atomicAdd(a + 0, v.x);
    atomicAdd(a + 1, v.y);
    atomicAdd(a + 2, v.z);
    atomicAdd(a + 3, v.w);
}

// ---------------- fp32 tiled GEMM: C = act(A[M,K] @ W[K,Nn] + bias) ----------
// BM=128, BN=64, BK=16, 256 threads, 8x4 per-thread tile.
__global__ __launch_bounds__(256) void gemm_kernel(
    const float* __restrict__ A, const float* __restrict__ W,
    const float* __restrict__ bias, float* __restrict__ C,
    int K, int Nn, int doRelu) {
    const int BM = 128, BN = 64, BK = 16;
    __shared__ __align__(16) float As[BK][BM + 1];
    __shared__ __align__(16) float Ws[BK][BN];

    int tid  = threadIdx.x;
    int tx   = tid & 15;   // col group: 4 cols
    int ty   = tid >> 4;   // row group: 8 rows
    int row0 = blockIdx.y * BM;
    int col0 = blockIdx.x * BN;

    int aRow = tid >> 2;        // 0..63
    int aCol = (tid & 3) * 4;   // 0,4,8,12
    int wRow = tid >> 4;        // 0..15
    int wCol = (tid & 15) * 4;  // 0..60

    float acc[8][4];
#pragma unroll
    for (int i = 0; i < 8; i++)
#pragma unroll
        for (int j = 0; j < 4; j++) acc[i][j] = 0.0f;

    for (int k0 = 0; k0 < K; k0 += BK) {
        float4 a0 = *(const float4*)(A + (size_t)(row0 + aRow) * K + k0 + aCol);
        float4 a1 = *(const float4*)(A + (size_t)(row0 + aRow + 64) * K + k0 + aCol);
        float4 wv = *(const float4*)(W + (size_t)(k0 + wRow) * Nn + col0 + wCol);

        As[aCol + 0][aRow] = a0.x;
        As[aCol + 1][aRow] = a0.y;
        As[aCol + 2][aRow] = a0.z;
        As[aCol + 3][aRow] = a0.w;
        As[aCol + 0][aRow + 64] = a1.x;
        As[aCol + 1][aRow + 64] = a1.y;
        As[aCol + 2][aRow + 64] = a1.z;
        As[aCol + 3][aRow + 64] = a1.w;
        *(float4*)&Ws[wRow][wCol] = wv;
        __syncthreads();

#pragma unroll
        for (int k = 0; k < BK; k++) {
            float b0 = Ws[k][tx * 4 + 0];
            float b1 = Ws[k][tx * 4 + 1];
            float b2 = Ws[k][tx * 4 + 2];
            float b3 = Ws[k][tx * 4 + 3];
#pragma unroll
            for (int i = 0; i < 8; i++) {
                float av = As[k][ty * 8 + i];
                acc[i][0] += av * b0;
                acc[i][1] += av * b1;
                acc[i][2] += av * b2;
                acc[i][3] += av * b3;
            }
        }
        __syncthreads();
    }

    float4 bv = *(const float4*)(bias + col0 + tx * 4);
#pragma unroll
    for (int i = 0; i < 8; i++) {
        float4 o;
        o.x = acc[i][0] + bv.x;
        o.y = acc[i][1] + bv.y;
        o.z = acc[i][2] + bv.z;
        o.w = acc[i][3] + bv.w;
        if (doRelu) {
            o.x = fmaxf(o.x, 0.0f);
            o.y = fmaxf(o.y, 0.0f);
            o.z = fmaxf(o.z, 0.0f);
            o.w = fmaxf(o.w, 0.0f);
        }
        *(float4*)(C + (size_t)(row0 + ty * 8 + i) * Nn + col0 + tx * 4) = o;
    }
}

// ---------------- pooling ----------------------------------------------------
__global__ void zero_kernel(float* __restrict__ out, int n_out) {
    int i = blockIdx.x * blockDim.x + threadIdx.x;
    if (i < n_out) out[i] = 0.0f;
    if (i < TSG) g_cnt[i] = 0.0f;
}

__global__ void pool_kernel(const int* __restrict__ batch,
                            const int* __restrict__ sgb,
                            float* __restrict__ sums, int Nnodes) {
    long long tid = (long long)blockIdx.x * blockDim.x + threadIdx.x;
    int node = (int)(tid >> 5);
    if (node >= Nnodes) return;
    int lane = (int)(tid & 31);
    int sg = g_off[batch[node]] + sgb[node];
    float4 v = ((const float4*)(g_h + (size_t)node * DD))[lane];
    float* s = sums + (size_t)sg * DD + lane * 4;
    atomicAdd(s + 0, v.x);
    atomicAdd(s + 1, v.y);
    atomicAdd(s + 2, v.z);
    atomicAdd(s + 3, v.w);
    if (lane == 0) atomicAdd(&g_cnt[sg], 1.0f);
}

__global__ void div_kernel(float* __restrict__ sums, int total) {
    int i = blockIdx.x * blockDim.x + threadIdx.x;
    if (i >= total) return;
    int sg = i / DD;
    sums[i] /= fmaxf(g_cnt[sg], 1.0f);
}

// ---------------- launch -----------------------------------------------------
extern "C" void kernel_launch(void* const* d_in, const int* in_sizes, int n_in,
                              void* d_out, int out_size) {
    const float* x    = (const float*)d_in[0];
    const int*   edge = (const int*)d_in[1];
    const int*   batch = (const int*)d_in[2];
    const int*   sgb   = (const int*)d_in[3];
    const int*   nsg   = (const int*)d_in[4];
    const float* W1  = (const float*)d_in[5];
    const float* b1  = (const float*)d_in[6];
    const float* W2  = (const float*)d_in[7];
    const float* b2  = (const float*)d_in[8];
    const float* eps = (const float*)d_in[9];
    float* out = (float*)d_out;

    int N = in_sizes[0] / DD;
    int E = in_sizes[1] / 2;
    int G = in_sizes[4];
    const int* src = edge;
    const int* dst = edge + E;

    void *ph, *pa, *py;
    cudaGetSymbolAddress(&ph, g_h);
    cudaGetSymbolAddress(&pa, g_agg);
    cudaGetSymbolAddress(&py, g_y);
    float* h   = (float*)ph;
    float* agg = (float*)pa;
    float* y   = (float*)py;

    prefix_kernel<<<1, 32>>>(nsg, G);

    for (int l = 0; l < LL; l++) {
        const float* hcur = (l == 0) ? x : h;
        int total4 = N * DD / 4;
        init_agg_kernel<<<(total4 + 255) / 256, 256>>>(hcur, eps, l, total4);
        scatter_kernel<<<(int)(((long long)E * 32 + 255) / 256), 256>>>(hcur, src, dst, E);

        // GEMM1: agg[N,128] @ W1_l[128,256] + b1, ReLU -> y
        dim3 g1(2 * DD / 64, N / 128);
        gemm_kernel<<<g1, 256>>>(agg, W1 + (size_t)l * DD * 2 * DD,
                                 b1 + (size_t)l * 2 * DD, y, DD, 2 * DD, 1);
        // GEMM2: y[N,256] @ W2_l[256,128] + b2, (ReLU if not last) -> h
        dim3 g2(DD / 64, N / 128);
        gemm_kernel<<<g2, 256>>>(y, W2 + (size_t)l * 2 * DD * DD,
                                 b2 + (size_t)l * DD, h, 2 * DD, DD,
                                 (l < LL - 1) ? 1 : 0);
    }

    int zn = out_size > TSG ? out_size : TSG;
    zero_kernel<<<(zn + 255) / 256, 256>>>(out, out_size);
    pool_kernel<<<(int)(((long long)N * 32 + 255) / 256), 256>>>(batch, sgb, out, N);
    div_kernel<<<(out_size + 255) / 256, 256>>>(out, out_size);
}

// round 2
// speedup vs baseline: 1.7842x; 1.7842x over previous
#include <cuda_runtime.h>
#include <cstddef>
#include <cstdint>

#define NN  102400
#define DD  128
#define LL  5
#define TSG 1024

// ---------------- scratch (static device globals; no allocation) -------------
__device__ float g_h[(size_t)NN * DD];        // 52.4 MB
__device__ float g_agg[(size_t)NN * DD];      // 52.4 MB
__device__ float g_y[(size_t)NN * 2 * DD];    // 104.8 MB
__device__ float g_cnt[TSG];
__device__ int   g_off[64];

// ---------------- graph-offset prefix (tiny, G=64) ---------------------------
__global__ void prefix_kernel(const int* __restrict__ ns, int G) {
    if (blockIdx.x == 0 && threadIdx.x == 0) {
        int a = 0;
        for (int g = 0; g < G; ++g) { g_off[g] = a; a += ns[g]; }
    }
}

// ---------------- agg = (1+eps_l) * h ----------------------------------------
__global__ void init_agg_kernel(const float* __restrict__ h,
                                const float* __restrict__ eps, int l,
                                int total4) {
    int i = blockIdx.x * blockDim.x + threadIdx.x;
    if (i >= total4) return;
    float e = 1.0f + eps[l];
    float4 v = ((const float4*)h)[i];
    v.x *= e; v.y *= e; v.z *= e; v.w *= e;
    ((float4*)g_agg)[i] = v;
}

// ---------------- warp-per-edge scatter: agg[dst] += h[src] ------------------
__device__ __forceinline__ void red_add_v4(float* p, float4 v) {
    asm volatile("red.global.add.v4.f32 [%0], {%1,%2,%3,%4};"
                 :: "l"(p), "f"(v.x), "f"(v.y), "f"(v.z), "f"(v.w)
                 : "memory");
}

__global__ void scatter_kernel(const float* __restrict__ h,
                               const int* __restrict__ src,
                               const int* __restrict__ dst, int E) {
    long long tid = (long long)blockIdx.x * blockDim.x + threadIdx.x;
    int e = (int)(tid >> 5);
    if (e >= E) return;
    int lane = (int)(tid & 31);
    int s = src[e], d = dst[e];
    float4 v = ((const float4*)(h + (size_t)s * DD))[lane];
    red_add_v4(g_agg + (size_t)d * DD + lane * 4, v);
}

// ---------------- tf32 tensor-core GEMM --------------------------------------
// C = act(A[M,K] @ W[K,Nn] + bias), BM=128 BN=64 BK=16, 256 thr (8 warps 4x2).
__device__ __forceinline__ uint32_t f2tf32(float f) {
    uint32_t r;
    asm("cvt.rna.tf32.f32 %0, %1;" : "=r"(r) : "f"(f));
    return r;
}

__global__ __launch_bounds__(256) void gemm_tc(
    const float* __restrict__ A, const float* __restrict__ W,
    const float* __restrict__ bias, float* __restrict__ C,
    int K, int Nn, int doRelu) {
    const int BM = 128, BN = 64, BK = 16;
    const int AST = BK + 4;                 // 20: row stride (80B, 16B-aligned)
    __shared__ __align__(16) uint32_t As[BM * AST + 8];
    __shared__ __align__(16) uint32_t Ws[BN * AST + 8];

    int tid  = threadIdx.x;
    int lane = tid & 31;
    int wid  = tid >> 5;
    int wm   = wid & 3;                     // warp row (0..3) -> 32 rows
    int wn   = wid >> 2;                    // warp col (0..1) -> 32 cols
    int row0 = blockIdx.y * BM;
    int col0 = blockIdx.x * BN;

    int ar = tid >> 2;                      // 0..63 (A rows, +64 second half)
    int ac = (tid & 3) * 4;                 // 0,4,8,12
    int kw = tid >> 4;                      // 0..15 (W k row)
    int nw = tid & 15;                      // W col group *4

    float acc[2][4][4];
#pragma unroll
    for (int mt = 0; mt < 2; mt++)
#pragma unroll
        for (int nt = 0; nt < 4; nt++)
#pragma unroll
            for (int j = 0; j < 4; j++) acc[mt][nt][j] = 0.0f;

    for (int k0 = 0; k0 < K; k0 += BK) {
        float4 a0 = *(const float4*)(A + (size_t)(row0 + ar) * K + k0 + ac);
        float4 a1 = *(const float4*)(A + (size_t)(row0 + ar + 64) * K + k0 + ac);
        float4 wv = *(const float4*)(W + (size_t)(k0 + kw) * Nn + col0 + nw * 4);

        uint32_t* pa0 = &As[ar * AST + ac];
        pa0[0] = f2tf32(a0.x); pa0[1] = f2tf32(a0.y);
        pa0[2] = f2tf32(a0.z); pa0[3] = f2tf32(a0.w);
        uint32_t* pa1 = &As[(ar + 64) * AST + ac];
        pa1[0] = f2tf32(a1.x); pa1[1] = f2tf32(a1.y);
        pa1[2] = f2tf32(a1.z); pa1[3] = f2tf32(a1.w);
        // W stored transposed: Ws[n][k]
        Ws[(nw * 4 + 0) * AST + kw] = f2tf32(wv.x);
        Ws[(nw * 4 + 1) * AST + kw] = f2tf32(wv.y);
        Ws[(nw * 4 + 2) * AST + kw] = f2tf32(wv.z);
        Ws[(nw * 4 + 3) * AST + kw] = f2tf32(wv.w);
        __syncthreads();

#pragma unroll
        for (int ks = 0; ks < 2; ks++) {
            uint32_t a[2][4], b[4][2];
#pragma unroll
            for (int mt = 0; mt < 2; mt++) {
                int sub = lane >> 3;                 // 0..3
                int r   = lane & 7;
                int m   = wm * 32 + mt * 16 + (sub & 1) * 8 + r;
                int kk  = ks * 8 + (sub >> 1) * 4;
                uint32_t addr = (uint32_t)__cvta_generic_to_shared(&As[m * AST + kk]);
                asm volatile(
                    "ldmatrix.sync.aligned.m8n8.x4.shared.b16 {%0,%1,%2,%3}, [%4];"
                    : "=r"(a[mt][0]), "=r"(a[mt][1]), "=r"(a[mt][2]), "=r"(a[mt][3])
                    : "r"(addr));
            }
#pragma unroll
            for (int nt = 0; nt < 4; nt++) {
                int sub = (lane >> 3) & 1;
                int r   = lane & 7;
                int n   = wn * 32 + nt * 8 + r;
                int kk  = ks * 8 + sub * 4;
                uint32_t addr = (uint32_t)__cvta_generic_to_shared(&Ws[n * AST + kk]);
                asm volatile(
                    "ldmatrix.sync.aligned.m8n8.x2.shared.b16 {%0,%1}, [%2];"
                    : "=r"(b[nt][0]), "=r"(b[nt][1])
                    : "r"(addr));
            }
#pragma unroll
            for (int mt = 0; mt < 2; mt++)
#pragma unroll
                for (int nt = 0; nt < 4; nt++) {
                    asm volatile(
                        "mma.sync.aligned.m16n8k8.row.col.f32.tf32.tf32.f32 "
                        "{%0,%1,%2,%3}, {%4,%5,%6,%7}, {%8,%9}, {%0,%1,%2,%3};"
                        : "+f"(acc[mt][nt][0]), "+f"(acc[mt][nt][1]),
                          "+f"(acc[mt][nt][2]), "+f"(acc[mt][nt][3])
                        : "r"(a[mt][0]), "r"(a[mt][1]), "r"(a[mt][2]), "r"(a[mt][3]),
                          "r"(b[nt][0]), "r"(b[nt][1]));
                }
        }
        __syncthreads();
    }

    // Epilogue: c0,c1 -> (row g, cols 2tg,2tg+1); c2,c3 -> row g+8
    int g  = lane >> 2;
    int tg = lane & 3;
#pragma unroll
    for (int mt = 0; mt < 2; mt++) {
#pragma unroll
        for (int nt = 0; nt < 4; nt++) {
            int col = col0 + wn * 32 + nt * 8 + tg * 2;
            float2 bv = *(const float2*)(bias + col);
            int r = row0 + wm * 32 + mt * 16 + g;
            float2 o0, o1;
            o0.x = acc[mt][nt][0] + bv.x;
            o0.y = acc[mt][nt][1] + bv.y;
            o1.x = acc[mt][nt][2] + bv.x;
            o1.y = acc[mt][nt][3] + bv.y;
            if (doRelu) {
                o0.x = fmaxf(o0.x, 0.0f); o0.y = fmaxf(o0.y, 0.0f);
                o1.x = fmaxf(o1.x, 0.0f); o1.y = fmaxf(o1.y, 0.0f);
            }
            *(float2*)(C + (size_t)r * Nn + col)       = o0;
            *(float2*)(C + (size_t)(r + 8) * Nn + col) = o1;
        }
    }
}

// ---------------- pooling ----------------------------------------------------
__global__ void zero_kernel(float* __restrict__ out, int n_out) {
    int i = blockIdx.x * blockDim.x + threadIdx.x;
    if (i < n_out) out[i] = 0.0f;
    if (i < TSG) g_cnt[i] = 0.0f;
}

__global__ void pool_kernel(const int* __restrict__ batch,
                            const int* __restrict__ sgb,
                            float* __restrict__ sums, int Nnodes) {
    long long tid = (long long)blockIdx.x * blockDim.x + threadIdx.x;
    int node = (int)(tid >> 5);
    if (node >= Nnodes) return;
    int lane = (int)(tid & 31);
    int sg = g_off[batch[node]] + sgb[node];
    float4 v = ((const float4*)(g_h + (size_t)node * DD))[lane];
    red_add_v4(sums + (size_t)sg * DD + lane * 4, v);
    if (lane == 0) atomicAdd(&g_cnt[sg], 1.0f);
}

__global__ void div_kernel(float* __restrict__ sums, int total) {
    int i = blockIdx.x * blockDim.x + threadIdx.x;
    if (i >= total) return;
    int sg = i / DD;
    sums[i] /= fmaxf(g_cnt[sg], 1.0f);
}

// ---------------- launch -----------------------------------------------------
extern "C" void kernel_launch(void* const* d_in, const int* in_sizes, int n_in,
                              void* d_out, int out_size) {
    const float* x     = (const float*)d_in[0];
    const int*   edge  = (const int*)d_in[1];
    const int*   batch = (const int*)d_in[2];
    const int*   sgb   = (const int*)d_in[3];
    const int*   nsg   = (const int*)d_in[4];
    const float* W1  = (const float*)d_in[5];
    const float* b1  = (const float*)d_in[6];
    const float* W2  = (const float*)d_in[7];
    const float* b2  = (const float*)d_in[8];
    const float* eps = (const float*)d_in[9];
    float* out = (float*)d_out;

    int N = in_sizes[0] / DD;
    int E = in_sizes[1] / 2;
    int G = in_sizes[4];
    const int* src = edge;
    const int* dst = edge + E;

    void *ph, *pa, *py;
    cudaGetSymbolAddress(&ph, g_h);
    cudaGetSymbolAddress(&pa, g_agg);
    cudaGetSymbolAddress(&py, g_y);
    float* h   = (float*)ph;
    float* agg = (float*)pa;
    float* y   = (float*)py;

    prefix_kernel<<<1, 32>>>(nsg, G);

    for (int l = 0; l < LL; l++) {
        const float* hcur = (l == 0) ? x : h;
        int total4 = N * DD / 4;
        init_agg_kernel<<<(total4 + 255) / 256, 256>>>(hcur, eps, l, total4);
        scatter_kernel<<<(int)(((long long)E * 32 + 255) / 256), 256>>>(hcur, src, dst, E);

        // GEMM1: agg[N,128] @ W1_l[128,256] + b1, ReLU -> y
        dim3 g1(2 * DD / 64, N / 128);
        gemm_tc<<<g1, 256>>>(agg, W1 + (size_t)l * DD * 2 * DD,
                             b1 + (size_t)l * 2 * DD, y, DD, 2 * DD, 1);
        // GEMM2: y[N,256] @ W2_l[256,128] + b2, (ReLU if not last) -> h
        dim3 g2(DD / 64, N / 128);
        gemm_tc<<<g2, 256>>>(y, W2 + (size_t)l * 2 * DD * DD,
                             b2 + (size_t)l * DD, h, 2 * DD, DD,
                             (l < LL - 1) ? 1 : 0);
    }

    int zn = out_size > TSG ? out_size : TSG;
    zero_kernel<<<(zn + 255) / 256, 256>>>(out, out_size);
    pool_kernel<<<(int)(((long long)N * 32 + 255) / 256), 256>>>(batch, sgb, out, N);
    div_kernel<<<(out_size + 255) / 256, 256>>>(out, out_size);
}

// round 3
// speedup vs baseline: 3.9179x; 2.1958x over previous
#include <cuda_runtime.h>
#include <cuda_fp16.h>
#include <cstdint>
#include <cstddef>

#define NN  102400
#define EE  819200
#define DD  128
#define LL  5
#define TSG 1024
#define NCHUNK 400          // NN / 256

// ---------------- scratch (static device globals) ----------------------------
__device__ float  g_h[(size_t)NN * DD];          // fp32 activations (52MB)
__device__ __half g_agg16[(size_t)NN * DD];      // GEMM1 input (26MB)
__device__ __half g_y16[(size_t)NN * 2 * DD];    // GEMM2 input (52MB)
__device__ __half g_w16t[(size_t)LL * 65536];    // transposed fp16 weights
__device__ int    g_rowptr[NN + 1];
__device__ int    g_cur[NN];
__device__ int    g_bsum[NCHUNK];
__device__ int    g_col[EE];
__device__ float  g_cnt[TSG];
__device__ int    g_off[64];

// ---------------- weight convert + transpose ---------------------------------
// layout per layer l (65536 halves): [0,32768): W1^T [n=256][k=128]
//                                    [32768,65536): W2^T [n=128][k=256]
__global__ void convw_kernel(const float* __restrict__ W1,
                             const float* __restrict__ W2) {
    int i = blockIdx.x * blockDim.x + threadIdx.x;
    if (i >= LL * 65536) return;
    int l = i >> 16, r = i & 65535;
    float v;
    if (r < 32768) {
        int n = r >> 7, k = r & 127;
        v = W1[(size_t)l * 32768 + k * 256 + n];
    } else {
        int r2 = r - 32768;
        int n = r2 >> 8, k = r2 & 255;
        v = W2[(size_t)l * 32768 + k * 128 + n];
    }
    g_w16t[i] = __float2half_rn(v);
}

// ---------------- CSR build ---------------------------------------------------
__global__ void hist_kernel(const int* __restrict__ dst, int E) {
    int e = blockIdx.x * blockDim.x + threadIdx.x;
    if (e < E) atomicAdd(&g_cur[dst[e]], 1);
}

__global__ void scan1_kernel() {
    __shared__ int s[256];
    int t = threadIdx.x, i = blockIdx.x * 256 + t;
    int v = g_cur[i];
    s[t] = v;
    __syncthreads();
#pragma unroll
    for (int o = 1; o < 256; o <<= 1) {
        int u = (t >= o) ? s[t - o] : 0;
        __syncthreads();
        s[t] += u;
        __syncthreads();
    }
    g_rowptr[i] = s[t] - v;                 // exclusive
    if (t == 255) g_bsum[blockIdx.x] = s[255];
}

__global__ void scan2_kernel() {
    __shared__ int s[512];
    int t = threadIdx.x;
    int v = (t < NCHUNK) ? g_bsum[t] : 0;
    s[t] = v;
    __syncthreads();
#pragma unroll
    for (int o = 1; o < 512; o <<= 1) {
        int u = (t >= o) ? s[t - o] : 0;
        __syncthreads();
        s[t] += u;
        __syncthreads();
    }
    if (t < NCHUNK) g_bsum[t] = s[t] - v;   // exclusive block offsets
}

__global__ void scan3_kernel(int E) {
    int i = blockIdx.x * blockDim.x + threadIdx.x;
    if (i < NN) g_rowptr[i] += g_bsum[i >> 8];
    if (i == 0) g_rowptr[NN] = E;
}

__global__ void fill_kernel(const int* __restrict__ src,
                            const int* __restrict__ dst, int E) {
    int e = blockIdx.x * blockDim.x + threadIdx.x;
    if (e >= E) return;
    int d = dst[e];
    int p = g_rowptr[d] + atomicAdd(&g_cur[d], 1);
    g_col[p] = src[e];
}

// ---------------- gather aggregation: agg16[d] = fp16((1+eps)h[d] + sum h[nb])
__global__ void gather_kernel(const float* __restrict__ h,
                              const float* __restrict__ eps, int l, int Nn) {
    long long tid = (long long)blockIdx.x * blockDim.x + threadIdx.x;
    int node = (int)(tid >> 5);
    if (node >= Nn) return;
    int lane = (int)(tid & 31);
    float e1 = 1.0f + eps[l];
    const float4* hv = (const float4*)h;
    float4 acc = hv[(size_t)node * 32 + lane];
    acc.x *= e1; acc.y *= e1; acc.z *= e1; acc.w *= e1;
    int s = g_rowptr[node], t = g_rowptr[node + 1];
    for (int i = s; i < t; i++) {
        int nb = g_col[i];
        float4 v = hv[(size_t)nb * 32 + lane];
        acc.x += v.x; acc.y += v.y; acc.z += v.z; acc.w += v.w;
    }
    __half2* o = (__half2*)g_agg16 + (size_t)node * 64 + lane * 2;
    o[0] = __floats2half2_rn(acc.x, acc.y);
    o[1] = __floats2half2_rn(acc.z, acc.w);
}

// ---------------- fp16 tensor-core GEMM, cp.async double-buffered ------------
// C = act(A[M,K]fp16 @ W[K,Nn] + bias), W given transposed fp16 [Nn][K].
// BM=128 BN=64 BK=32, 256 thr, 8 warps (4m x 2n), warp tile 32x32.
#define CP16(smb, g) \
    asm volatile("cp.async.cg.shared.global [%0], [%1], 16;" :: "r"(smb), "l"(g))

__global__ __launch_bounds__(256) void gemm16_kernel(
    const __half* __restrict__ A, const __half* __restrict__ Wt,
    const float* __restrict__ bias, void* __restrict__ Cout,
    int K, int Nn, int doRelu, int outHalf) {
    extern __shared__ char sm[];
    const int wstrideB = (K + 8) * 2;           // bytes per Ws row (16B mult)
    const int WsB = 64 * wstrideB;              // Ws region size
    const int stB = 128 * 80;                   // A stage size (row stride 80B)
    uint32_t sbase = (uint32_t)__cvta_generic_to_shared(sm);
    uint32_t wsb = sbase;
    uint32_t asb = sbase + WsB;

    int tid  = threadIdx.x;
    int lane = tid & 31;
    int wid  = tid >> 5;
    int wm   = wid & 3;
    int wn   = wid >> 2;
    int row0 = blockIdx.y * 128;
    int col0 = blockIdx.x * 64;

    // ---- async W preload: rows n of Wt (K fp16 each) ----
    {
        int rw = tid >> 2, ch = tid & 3;
        int per = (K * 2) / 4;                  // bytes per thread (64 or 128)
        const char* g = (const char*)(Wt + (size_t)(col0 + rw) * K) + ch * per;
        uint32_t s = wsb + rw * wstrideB + ch * per;
        for (int o = 0; o < per; o += 16) CP16(s + o, g + o);
    }
    // ---- A stage issue ----
    int ra = tid >> 1, ha = tid & 1;
    const char* Agb = (const char*)(A + (size_t)(row0 + ra) * K) + ha * 32;
    uint32_t As0 = asb + ra * 80 + ha * 32;
    {
        const char* g = Agb;                    // k0 = 0
        CP16(As0, g); CP16(As0 + 16, g + 16);
        asm volatile("cp.async.commit_group;");
    }

    float acc[2][4][4];
#pragma unroll
    for (int mt = 0; mt < 2; mt++)
#pragma unroll
        for (int nt = 0; nt < 4; nt++)
#pragma unroll
            for (int j = 0; j < 4; j++) acc[mt][nt][j] = 0.0f;

    int nk = K >> 5;
    for (int k0 = 0; k0 < nk; k0++) {
        int st = k0 & 1;
        if (k0 + 1 < nk) {
            const char* g = Agb + (size_t)(k0 + 1) * 64;
            uint32_t s = As0 + ((st ^ 1) ? stB : 0);
            CP16(s, g); CP16(s + 16, g + 16);
            asm volatile("cp.async.commit_group;");
            asm volatile("cp.async.wait_group 1;");
        } else {
            asm volatile("cp.async.wait_group 0;");
        }
        __syncthreads();

        uint32_t ab = asb + (st ? stB : 0);
#pragma unroll
        for (int ks = 0; ks < 2; ks++) {
            uint32_t a[2][4], b[4][2];
            int r8  = lane & 7;
            int sel = lane >> 3;
#pragma unroll
            for (int mt = 0; mt < 2; mt++) {
                int m  = wm * 32 + mt * 16 + (sel & 1) * 8 + r8;
                int kb = ks * 32 + ((sel >> 1) & 1) * 16;
                uint32_t ad = ab + m * 80 + kb;
                asm volatile(
                    "ldmatrix.sync.aligned.m8n8.x4.shared.b16 {%0,%1,%2,%3}, [%4];"
                    : "=r"(a[mt][0]), "=r"(a[mt][1]), "=r"(a[mt][2]), "=r"(a[mt][3])
                    : "r"(ad));
            }
            int ll  = lane & 15;
            int bs  = ll >> 3;
            int br  = ll & 7;
#pragma unroll
            for (int nt = 0; nt < 4; nt++) {
                int n  = wn * 32 + nt * 8 + br;
                int kb = k0 * 64 + ks * 32 + bs * 16;
                uint32_t ad = wsb + n * wstrideB + kb;
                asm volatile(
                    "ldmatrix.sync.aligned.m8n8.x2.shared.b16 {%0,%1}, [%2];"
                    : "=r"(b[nt][0]), "=r"(b[nt][1]) : "r"(ad));
            }
#pragma unroll
            for (int mt = 0; mt < 2; mt++)
#pragma unroll
                for (int nt = 0; nt < 4; nt++) {
                    asm volatile(
                        "mma.sync.aligned.m16n8k16.row.col.f32.f16.f16.f32 "
                        "{%0,%1,%2,%3}, {%4,%5,%6,%7}, {%8,%9}, {%0,%1,%2,%3};"
                        : "+f"(acc[mt][nt][0]), "+f"(acc[mt][nt][1]),
                          "+f"(acc[mt][nt][2]), "+f"(acc[mt][nt][3])
                        : "r"(a[mt][0]), "r"(a[mt][1]), "r"(a[mt][2]), "r"(a[mt][3]),
                          "r"(b[nt][0]), "r"(b[nt][1]));
                }
        }
        __syncthreads();
    }

    // ---- epilogue ----
    int g  = lane >> 2;
    int tg = lane & 3;
#pragma unroll
    for (int mt = 0; mt < 2; mt++) {
#pragma unroll
        for (int nt = 0; nt < 4; nt++) {
            int col = col0 + wn * 32 + nt * 8 + tg * 2;
            float2 bv = *(const float2*)(bias + col);
            int r0 = row0 + wm * 32 + mt * 16 + g;
            float2 o0, o1;
            o0.x = acc[mt][nt][0] + bv.x;
            o0.y = acc[mt][nt][1] + bv.y;
            o1.x = acc[mt][nt][2] + bv.x;
            o1.y = acc[mt][nt][3] + bv.y;
            if (doRelu) {
                o0.x = fmaxf(o0.x, 0.0f); o0.y = fmaxf(o0.y, 0.0f);
                o1.x = fmaxf(o1.x, 0.0f); o1.y = fmaxf(o1.y, 0.0f);
            }
            if (outHalf) {
                __half* C = (__half*)Cout;
                *(__half2*)(C + (size_t)r0 * Nn + col) = __floats2half2_rn(o0.x, o0.y);
                *(__half2*)(C + (size_t)(r0 + 8) * Nn + col) = __floats2half2_rn(o1.x, o1.y);
            } else {
                float* C = (float*)Cout;
                *(float2*)(C + (size_t)r0 * Nn + col)       = o0;
                *(float2*)(C + (size_t)(r0 + 8) * Nn + col) = o1;
            }
        }
    }
}

// ---------------- pooling ----------------------------------------------------
__device__ __forceinline__ void red_add_v4(float* p, float4 v) {
    asm volatile("red.global.add.v4.f32 [%0], {%1,%2,%3,%4};"
                 :: "l"(p), "f"(v.x), "f"(v.y), "f"(v.z), "f"(v.w)
                 : "memory");
}

__global__ void prefix_kernel(const int* __restrict__ ns, int G) {
    if (blockIdx.x == 0 && threadIdx.x == 0) {
        int a = 0;
        for (int g = 0; g < G; ++g) { g_off[g] = a; a += ns[g]; }
    }
}

__global__ void zero_kernel(float* __restrict__ out, int n_out) {
    int i = blockIdx.x * blockDim.x + threadIdx.x;
    if (i < n_out) out[i] = 0.0f;
    if (i < TSG) g_cnt[i] = 0.0f;
}

__global__ void pool_kernel(const int* __restrict__ batch,
                            const int* __restrict__ sgb,
                            float* __restrict__ sums, int Nnodes) {
    long long tid = (long long)blockIdx.x * blockDim.x + threadIdx.x;
    int node = (int)(tid >> 5);
    if (node >= Nnodes) return;
    int lane = (int)(tid & 31);
    int sg = g_off[batch[node]] + sgb[node];
    float4 v = ((const float4*)g_h)[(size_t)node * 32 + lane];
    red_add_v4(sums + (size_t)sg * DD + lane * 4, v);
    if (lane == 0) atomicAdd(&g_cnt[sg], 1.0f);
}

__global__ void div_kernel(float* __restrict__ sums, int total) {
    int i = blockIdx.x * blockDim.x + threadIdx.x;
    if (i >= total) return;
    sums[i] /= fmaxf(g_cnt[i / DD], 1.0f);
}

// ---------------- launch -----------------------------------------------------
extern "C" void kernel_launch(void* const* d_in, const int* in_sizes, int n_in,
                              void* d_out, int out_size) {
    const float* x     = (const float*)d_in[0];
    const int*   edge  = (const int*)d_in[1];
    const int*   batch = (const int*)d_in[2];
    const int*   sgb   = (const int*)d_in[3];
    const int*   nsg   = (const int*)d_in[4];
    const float* W1  = (const float*)d_in[5];
    const float* b1  = (const float*)d_in[6];
    const float* W2  = (const float*)d_in[7];
    const float* b2  = (const float*)d_in[8];
    const float* eps = (const float*)d_in[9];
    float* out = (float*)d_out;

    int N = in_sizes[0] / DD;
    int E = in_sizes[1] / 2;
    int G = in_sizes[4];
    const int* src = edge;
    const int* dst = edge + E;

    void *ph, *pa, *py, *pw, *pc;
    cudaGetSymbolAddress(&ph, g_h);
    cudaGetSymbolAddress(&pa, g_agg16);
    cudaGetSymbolAddress(&py, g_y16);
    cudaGetSymbolAddress(&pw, g_w16t);
    cudaGetSymbolAddress(&pc, g_cur);
    float*  h     = (float*)ph;
    __half* agg16 = (__half*)pa;
    __half* y16   = (__half*)py;
    __half* w16t  = (__half*)pw;

    static bool attrSet = false;
    if (!attrSet) {
        cudaFuncSetAttribute(gemm16_kernel,
                             cudaFuncAttributeMaxDynamicSharedMemorySize, 60000);
        attrSet = true;
    }

    // one-time per launch: weights + CSR
    convw_kernel<<<(LL * 65536 + 255) / 256, 256>>>(W1, W2);
    prefix_kernel<<<1, 32>>>(nsg, G);
    cudaMemsetAsync(pc, 0, (size_t)NN * 4, 0);
    hist_kernel<<<(E + 255) / 256, 256>>>(dst, E);
    scan1_kernel<<<NCHUNK, 256>>>();
    scan2_kernel<<<1, 512>>>();
    scan3_kernel<<<(NN + 255) / 256, 256>>>(E);
    cudaMemsetAsync(pc, 0, (size_t)NN * 4, 0);
    fill_kernel<<<(E + 255) / 256, 256>>>(src, dst, E);

    int smem1 = 64 * (128 + 8) * 2 + 2 * 128 * 80;   // 37888
    int smem2 = 64 * (256 + 8) * 2 + 2 * 128 * 80;   // 54272

    for (int l = 0; l < LL; l++) {
        const float* hcur = (l == 0) ? x : h;
        gather_kernel<<<(int)(((long long)N * 32 + 255) / 256), 256>>>(hcur, eps, l, N);
        // GEMM1: agg16[N,128] @ W1 -> y16 [N,256], ReLU
        gemm16_kernel<<<dim3(4, N / 128), 256, smem1>>>(
            agg16, w16t + (size_t)l * 65536, b1 + (size_t)l * 256,
            y16, 128, 256, 1, 1);
        // GEMM2: y16[N,256] @ W2 -> h [N,128] fp32, ReLU unless last
        gemm16_kernel<<<dim3(2, N / 128), 256, smem2>>>(
            y16, w16t + (size_t)l * 65536 + 32768, b2 + (size_t)l * 128,
            h, 256, 128, (l < LL - 1) ? 1 : 0, 0);
    }

    zero_kernel<<<(out_size + 255) / 256, 256>>>(out, out_size);
    pool_kernel<<<(int)(((long long)N * 32 + 255) / 256), 256>>>(batch, sgb, out, N);
    div_kernel<<<(out_size + 255) / 256, 256>>>(out, out_size);
}

// round 5
// speedup vs baseline: 4.1093x; 1.0489x over previous
#include <cuda_runtime.h>
#include <cuda_fp16.h>
#include <cstdint>
#include <cstddef>

#define NN  102400
#define EE  819200
#define DD  128
#define LL  5
#define TSG 1024
#define NCHUNK 400          // NN / 256

// ---------------- scratch (static device globals) ----------------------------
__device__ float  g_h[(size_t)NN * DD];          // fp32 final activations (pool)
__device__ __half g_hh16[(size_t)NN * DD];       // fp16 activations (gather in)
__device__ __half g_agg16[(size_t)NN * DD];      // GEMM1 input
__device__ __half g_y16[(size_t)NN * 2 * DD];    // GEMM2 input
__device__ __half g_w16t[(size_t)LL * 65536];    // transposed fp16 weights
__device__ int    g_rowptr[NN + 1];
__device__ int    g_cur[NN];
__device__ int    g_bsum[NCHUNK];
__device__ int    g_col[EE];
__device__ float  g_cnt[TSG];
__device__ int    g_off[64];

// ---------------- weight convert + transpose ---------------------------------
// per layer l: [0,32768): W1^T [n=256][k=128]; [32768,65536): W2^T [n=128][k=256]
__global__ void convw_kernel(const float* __restrict__ W1,
                             const float* __restrict__ W2) {
    int i = blockIdx.x * blockDim.x + threadIdx.x;
    if (i >= LL * 65536) return;
    int l = i >> 16, r = i & 65535;
    float v;
    if (r < 32768) {
        int n = r >> 7, k = r & 127;
        v = W1[(size_t)l * 32768 + k * 256 + n];
    } else {
        int r2 = r - 32768;
        int n = r2 >> 8, k = r2 & 255;
        v = W2[(size_t)l * 32768 + k * 128 + n];
    }
    g_w16t[i] = __float2half_rn(v);
}

// ---------------- CSR build ---------------------------------------------------
__global__ void hist_kernel(const int* __restrict__ dst, int E) {
    int e = blockIdx.x * blockDim.x + threadIdx.x;
    if (e < E) atomicAdd(&g_cur[dst[e]], 1);
}

__global__ void scan1_kernel() {
    __shared__ int s[256];
    int t = threadIdx.x, i = blockIdx.x * 256 + t;
    int v = g_cur[i];
    s[t] = v;
    __syncthreads();
#pragma unroll
    for (int o = 1; o < 256; o <<= 1) {
        int u = (t >= o) ? s[t - o] : 0;
        __syncthreads();
        s[t] += u;
        __syncthreads();
    }
    g_rowptr[i] = s[t] - v;
    if (t == 255) g_bsum[blockIdx.x] = s[255];
}

__global__ void scan2_kernel() {
    __shared__ int s[512];
    int t = threadIdx.x;
    int v = (t < NCHUNK) ? g_bsum[t] : 0;
    s[t] = v;
    __syncthreads();
#pragma unroll
    for (int o = 1; o < 512; o <<= 1) {
        int u = (t >= o) ? s[t - o] : 0;
        __syncthreads();
        s[t] += u;
        __syncthreads();
    }
    if (t < NCHUNK) g_bsum[t] = s[t] - v;
}

__global__ void scan3_kernel(int E) {
    int i = blockIdx.x * blockDim.x + threadIdx.x;
    if (i < NN) g_rowptr[i] += g_bsum[i >> 8];
    if (i == 0) g_rowptr[NN] = E;
}

__global__ void fill_kernel(const int* __restrict__ src,
                            const int* __restrict__ dst, int E) {
    int e = blockIdx.x * blockDim.x + threadIdx.x;
    if (e >= E) return;
    int d = dst[e];
    int p = g_rowptr[d] + atomicAdd(&g_cur[d], 1);
    g_col[p] = src[e];
}

// ---------------- gather: agg16[d] = fp16((1+eps)h[d] + sum h[nb]) ------------
// one warp per node; lane covers 4 of 128 features (uint2 fp16 / float4 fp32)
__device__ __forceinline__ void addh4(float* acc, const __half* base,
                                      int node, int lane, float w) {
    uint2 v = ((const uint2*)(base + (size_t)node * DD))[lane];
    float2 f0 = __half22float2(*(const __half2*)&v.x);
    float2 f1 = __half22float2(*(const __half2*)&v.y);
    acc[0] += w * f0.x; acc[1] += w * f0.y;
    acc[2] += w * f1.x; acc[3] += w * f1.y;
}

__global__ void gather_kernel(const float* __restrict__ xf,
                              const float* __restrict__ eps, int l, int useH,
                              int Nn) {
    long long tid = (long long)blockIdx.x * blockDim.x + threadIdx.x;
    int node = (int)(tid >> 5);
    if (node >= Nn) return;
    int lane = (int)(tid & 31);
    float e1 = 1.0f + eps[l];
    float acc[4] = {0.0f, 0.0f, 0.0f, 0.0f};

    int s = g_rowptr[node], t = g_rowptr[node + 1];
    if (useH) {
        addh4(acc, g_hh16, node, lane, e1);
        for (int i = s; i < t; i++) addh4(acc, g_hh16, g_col[i], lane, 1.0f);
    } else {
        const float4* xv = (const float4*)xf;
        float4 a = xv[(size_t)node * 32 + lane];
        acc[0] = e1 * a.x; acc[1] = e1 * a.y;
        acc[2] = e1 * a.z; acc[3] = e1 * a.w;
        for (int i = s; i < t; i++) {
            float4 v = xv[(size_t)g_col[i] * 32 + lane];
            acc[0] += v.x; acc[1] += v.y; acc[2] += v.z; acc[3] += v.w;
        }
    }
    __half2 h0 = __floats2half2_rn(acc[0], acc[1]);
    __half2 h1 = __floats2half2_rn(acc[2], acc[3]);
    uint2 o = {*(uint32_t*)&h0, *(uint32_t*)&h1};
    ((uint2*)(g_agg16 + (size_t)node * DD))[lane] = o;
}

// ---------------- fp16 mma.sync GEMM, cp.async double-buffered ----------------
// C = act(A[M,K]fp16 @ W[K,Nn] + bias), W transposed fp16 [Nn][K].
// BM=128 BN=128 BK=32, 256 thr, 8 warps (2m x 4n), warp tile 64x32.
#define CP16(smb, g) \
    asm volatile("cp.async.cg.shared.global [%0], [%1], 16;" :: "r"(smb), "l"(g))

__global__ __launch_bounds__(256) void gemm16_kernel(
    const __half* __restrict__ A, const __half* __restrict__ Wt,
    const float* __restrict__ bias, __half* __restrict__ C16,
    float* __restrict__ C32, int K, int Nn, int doRelu, int write32) {
    extern __shared__ char sm[];
    const int wstrideB = (K + 8) * 2;           // bytes per Ws row (16B mult)
    const int WsB = 128 * wstrideB;             // Ws region (BN=128 rows)
    const int stB = 128 * 80;                   // A stage size (row stride 80B)
    uint32_t sbase = (uint32_t)__cvta_generic_to_shared(sm);
    uint32_t wsb = sbase;
    uint32_t asb = sbase + WsB;

    int tid  = threadIdx.x;
    int lane = tid & 31;
    int wid  = tid >> 5;
    int wm   = wid & 1;                         // 2 warp-rows of 64
    int wn   = wid >> 1;                        // 4 warp-cols of 32
    int row0 = blockIdx.y * 128;
    int col0 = blockIdx.x * 128;

    // ---- async W preload: 128 rows of Wt, 2 threads/row ----
    {
        int rw = tid >> 1, ch = tid & 1;
        int per = K;                            // bytes per thread = K*2/2
        const char* g = (const char*)(Wt + (size_t)(col0 + rw) * K) + ch * per;
        uint32_t s = wsb + rw * wstrideB + ch * per;
        for (int o = 0; o < per; o += 16) CP16(s + o, g + o);
    }
    // ---- A stage 0 ----
    int ra = tid >> 1, ha = tid & 1;
    const char* Agb = (const char*)(A + (size_t)(row0 + ra) * K) + ha * 32;
    uint32_t As0 = asb + ra * 80 + ha * 32;
    {
        CP16(As0, Agb); CP16(As0 + 16, Agb + 16);
        asm volatile("cp.async.commit_group;");
    }

    float acc[4][4][4];
#pragma unroll
    for (int mt = 0; mt < 4; mt++)
#pragma unroll
        for (int nt = 0; nt < 4; nt++)
#pragma unroll
            for (int j = 0; j < 4; j++) acc[mt][nt][j] = 0.0f;

    int nk = K >> 5;
    for (int k0 = 0; k0 < nk; k0++) {
        int st = k0 & 1;
        if (k0 + 1 < nk) {
            const char* g = Agb + (size_t)(k0 + 1) * 64;
            uint32_t s = As0 + ((st ^ 1) ? stB : 0);
            CP16(s, g); CP16(s + 16, g + 16);
            asm volatile("cp.async.commit_group;");
            asm volatile("cp.async.wait_group 1;");
        } else {
            asm volatile("cp.async.wait_group 0;");
        }
        __syncthreads();

        uint32_t ab = asb + (st ? stB : 0);
#pragma unroll
        for (int ks = 0; ks < 2; ks++) {
            uint32_t a[4][4], b[4][2];
            int r8  = lane & 7;
            int sel = lane >> 3;
#pragma unroll
            for (int mt = 0; mt < 4; mt++) {
                int m  = wm * 64 + mt * 16 + (sel & 1) * 8 + r8;
                int kb = ks * 32 + ((sel >> 1) & 1) * 16;
                uint32_t ad = ab + m * 80 + kb;
                asm volatile(
                    "ldmatrix.sync.aligned.m8n8.x4.shared.b16 {%0,%1,%2,%3}, [%4];"
                    : "=r"(a[mt][0]), "=r"(a[mt][1]), "=r"(a[mt][2]), "=r"(a[mt][3])
                    : "r"(ad));
            }
            int ll  = lane & 15;
            int bs  = ll >> 3;
            int br  = ll & 7;
#pragma unroll
            for (int nt = 0; nt < 4; nt++) {
                int n  = wn * 32 + nt * 8 + br;
                int kb = k0 * 64 + ks * 32 + bs * 16;
                uint32_t ad = wsb + n * wstrideB + kb;
                asm volatile(
                    "ldmatrix.sync.aligned.m8n8.x2.shared.b16 {%0,%1}, [%2];"
                    : "=r"(b[nt][0]), "=r"(b[nt][1]) : "r"(ad));
            }
#pragma unroll
            for (int mt = 0; mt < 4; mt++)
#pragma unroll
                for (int nt = 0; nt < 4; nt++) {
                    asm volatile(
                        "mma.sync.aligned.m16n8k16.row.col.f32.f16.f16.f32 "
                        "{%0,%1,%2,%3}, {%4,%5,%6,%7}, {%8,%9}, {%0,%1,%2,%3};"
                        : "+f"(acc[mt][nt][0]), "+f"(acc[mt][nt][1]),
                          "+f"(acc[mt][nt][2]), "+f"(acc[mt][nt][3])
                        : "r"(a[mt][0]), "r"(a[mt][1]), "r"(a[mt][2]), "r"(a[mt][3]),
                          "r"(b[nt][0]), "r"(b[nt][1]));
                }
        }
        __syncthreads();
    }

    // ---- epilogue ----
    int g  = lane >> 2;
    int tg = lane & 3;
#pragma unroll
    for (int mt = 0; mt < 4; mt++) {
#pragma unroll
        for (int nt = 0; nt < 4; nt++) {
            int col = col0 + wn * 32 + nt * 8 + tg * 2;
            float2 bv = *(const float2*)(bias + col);
            int r0 = row0 + wm * 64 + mt * 16 + g;
            float2 o0, o1;
            o0.x = acc[mt][nt][0] + bv.x;
            o0.y = acc[mt][nt][1] + bv.y;
            o1.x = acc[mt][nt][2] + bv.x;
            o1.y = acc[mt][nt][3] + bv.y;
            if (doRelu) {
                o0.x = fmaxf(o0.x, 0.0f); o0.y = fmaxf(o0.y, 0.0f);
                o1.x = fmaxf(o1.x, 0.0f); o1.y = fmaxf(o1.y, 0.0f);
            }
            __half2 p0 = __floats2half2_rn(o0.x, o0.y);
            __half2 p1 = __floats2half2_rn(o1.x, o1.y);
            *(__half2*)(C16 + (size_t)r0 * Nn + col)       = p0;
            *(__half2*)(C16 + (size_t)(r0 + 8) * Nn + col) = p1;
            if (write32) {
                *(float2*)(C32 + (size_t)r0 * Nn + col)       = o0;
                *(float2*)(C32 + (size_t)(r0 + 8) * Nn + col) = o1;
            }
        }
    }
}

// ---------------- pooling -----------------------------------------------------
__device__ __forceinline__ void red_add_v4(float* p, float4 v) {
    asm volatile("red.global.add.v4.f32 [%0], {%1,%2,%3,%4};"
                 :: "l"(p), "f"(v.x), "f"(v.y), "f"(v.z), "f"(v.w)
                 : "memory");
}

__global__ void prefix_kernel(const int* __restrict__ ns, int G) {
    if (blockIdx.x == 0 && threadIdx.x == 0) {
        int a = 0;
        for (int g = 0; g < G; ++g) { g_off[g] = a; a += ns[g]; }
    }
}

__global__ void zero_kernel(float* __restrict__ out, int n_out) {
    int i = blockIdx.x * blockDim.x + threadIdx.x;
    if (i < n_out) out[i] = 0.0f;
    if (i < TSG) g_cnt[i] = 0.0f;
}

__global__ void pool_kernel(const int* __restrict__ batch,
                            const int* __restrict__ sgb,
                            float* __restrict__ sums, int Nnodes) {
    long long tid = (long long)blockIdx.x * blockDim.x + threadIdx.x;
    int node = (int)(tid >> 5);
    if (node >= Nnodes) return;
    int lane = (int)(tid & 31);
    int sg = g_off[batch[node]] + sgb[node];
    float4 v = ((const float4*)g_h)[(size_t)node * 32 + lane];
    red_add_v4(sums + (size_t)sg * DD + lane * 4, v);
    if (lane == 0) atomicAdd(&g_cnt[sg], 1.0f);
}

__global__ void div_kernel(float* __restrict__ sums, int total) {
    int i = blockIdx.x * blockDim.x + threadIdx.x;
    if (i >= total) return;
    sums[i] /= fmaxf(g_cnt[i / DD], 1.0f);
}

// ---------------- launch ------------------------------------------------------
extern "C" void kernel_launch(void* const* d_in, const int* in_sizes, int n_in,
                              void* d_out, int out_size) {
    const float* x     = (const float*)d_in[0];
    const int*   edge  = (const int*)d_in[1];
    const int*   batch = (const int*)d_in[2];
    const int*   sgb   = (const int*)d_in[3];
    const int*   nsg   = (const int*)d_in[4];
    const float* W1  = (const float*)d_in[5];
    const float* b1  = (const float*)d_in[6];
    const float* W2  = (const float*)d_in[7];
    const float* b2  = (const float*)d_in[8];
    const float* eps = (const float*)d_in[9];
    float* out = (float*)d_out;

    int N = in_sizes[0] / DD;
    int E = in_sizes[1] / 2;
    int G = in_sizes[4];
    const int* src = edge;
    const int* dst = edge + E;

    void *ph, *ph16, *pa, *py, *pw, *pc;
    cudaGetSymbolAddress(&ph, g_h);
    cudaGetSymbolAddress(&ph16, g_hh16);
    cudaGetSymbolAddress(&pa, g_agg16);
    cudaGetSymbolAddress(&py, g_y16);
    cudaGetSymbolAddress(&pw, g_w16t);
    cudaGetSymbolAddress(&pc, g_cur);
    float*  h     = (float*)ph;
    __half* h16   = (__half*)ph16;
    __half* agg16 = (__half*)pa;
    __half* y16   = (__half*)py;
    __half* w16t  = (__half*)pw;

    static bool attrSet = false;
    if (!attrSet) {
        cudaFuncSetAttribute(gemm16_kernel,
                             cudaFuncAttributeMaxDynamicSharedMemorySize, 92160);
        attrSet = true;
    }

    // one-time per launch: weights + CSR
    convw_kernel<<<(LL * 65536 + 255) / 256, 256>>>(W1, W2);
    prefix_kernel<<<1, 32>>>(nsg, G);
    cudaMemsetAsync(pc, 0, (size_t)NN * 4, 0);
    hist_kernel<<<(E + 255) / 256, 256>>>(dst, E);
    scan1_kernel<<<NCHUNK, 256>>>();
    scan2_kernel<<<1, 512>>>();
    scan3_kernel<<<(NN + 255) / 256, 256>>>(E);
    cudaMemsetAsync(pc, 0, (size_t)NN * 4, 0);
    fill_kernel<<<(E + 255) / 256, 256>>>(src, dst, E);

    int smem1 = 128 * (128 + 8) * 2 + 2 * 128 * 80;   // 55296
    int smem2 = 128 * (256 + 8) * 2 + 2 * 128 * 80;   // 88064

    for (int l = 0; l < LL; l++) {
        gather_kernel<<<(int)(((long long)N * 32 + 255) / 256), 256>>>(
            x, eps, l, (l > 0) ? 1 : 0, N);
        // GEMM1: agg16[N,128] @ W1 -> y16[N,256], ReLU
        gemm16_kernel<<<dim3(2, N / 128), 256, smem1>>>(
            agg16, w16t + (size_t)l * 65536, b1 + (size_t)l * 256,
            y16, (float*)nullptr, 128, 256, 1, 0);
        // GEMM2: y16[N,256] @ W2 -> h16 (+ fp32 h on last layer)
        gemm16_kernel<<<dim3(1, N / 128), 256, smem2>>>(
            y16, w16t + (size_t)l * 65536 + 32768, b2 + (size_t)l * 128,
            h16, h, 256, 128, (l < LL - 1) ? 1 : 0, (l == LL - 1) ? 1 : 0);
    }

    zero_kernel<<<(out_size + 255) / 256, 256>>>(out, out_size);
    pool_kernel<<<(int)(((long long)N * 32 + 255) / 256), 256>>>(batch, sgb, out, N);
    div_kernel<<<(out_size + 255) / 256, 256>>>(out, out_size);
}

// round 6
// speedup vs baseline: 5.6855x; 1.3836x over previous
#include <cuda_runtime.h>
#include <cuda_fp16.h>
#include <cstdint>
#include <cstddef>

#define NN  102400
#define EE  819200
#define DD  128
#define LL  5
#define TSG 1024
#define NCHUNK 400          // NN / 256

// ---------------- scratch (static device globals) ----------------------------
__device__ float  g_h[(size_t)NN * DD];          // fp32 final activations (pool)
__device__ __half g_hh16[(size_t)NN * DD];       // fp16 activations (gather in)
__device__ __half g_agg16[(size_t)NN * DD];      // MLP input
__device__ __half g_w16t[(size_t)LL * 65536];    // transposed fp16 weights
__device__ int    g_rowptr[NN + 1];
__device__ int    g_cur[NN];
__device__ int    g_bsum[NCHUNK];
__device__ int    g_col[EE];
__device__ float  g_cnt[TSG];
__device__ int    g_off[64];

// ---------------- weight convert + transpose ---------------------------------
// per layer l: [0,32768): W1^T [n=256][k=128]; [32768,65536): W2^T [n=128][k=256]
__global__ void convw_kernel(const float* __restrict__ W1,
                             const float* __restrict__ W2) {
    int i = blockIdx.x * blockDim.x + threadIdx.x;
    if (i >= LL * 65536) return;
    int l = i >> 16, r = i & 65535;
    float v;
    if (r < 32768) {
        int n = r >> 7, k = r & 127;
        v = W1[(size_t)l * 32768 + k * 256 + n];
    } else {
        int r2 = r - 32768;
        int n = r2 >> 8, k = r2 & 255;
        v = W2[(size_t)l * 32768 + k * 128 + n];
    }
    g_w16t[i] = __float2half_rn(v);
}

// ---------------- CSR build ---------------------------------------------------
__global__ void hist_kernel(const int* __restrict__ dst, int E) {
    int e = blockIdx.x * blockDim.x + threadIdx.x;
    if (e < E) atomicAdd(&g_cur[dst[e]], 1);
}

__global__ void scan1_kernel() {
    __shared__ int s[256];
    int t = threadIdx.x, i = blockIdx.x * 256 + t;
    int v = g_cur[i];
    s[t] = v;
    __syncthreads();
#pragma unroll
    for (int o = 1; o < 256; o <<= 1) {
        int u = (t >= o) ? s[t - o] : 0;
        __syncthreads();
        s[t] += u;
        __syncthreads();
    }
    g_rowptr[i] = s[t] - v;
    if (t == 255) g_bsum[blockIdx.x] = s[255];
}

__global__ void scan2_kernel() {
    __shared__ int s[512];
    int t = threadIdx.x;
    int v = (t < NCHUNK) ? g_bsum[t] : 0;
    s[t] = v;
    __syncthreads();
#pragma unroll
    for (int o = 1; o < 512; o <<= 1) {
        int u = (t >= o) ? s[t - o] : 0;
        __syncthreads();
        s[t] += u;
        __syncthreads();
    }
    if (t < NCHUNK) g_bsum[t] = s[t] - v;
}

__global__ void scan3_kernel(int E) {
    int i = blockIdx.x * blockDim.x + threadIdx.x;
    if (i < NN) g_rowptr[i] += g_bsum[i >> 8];
    if (i == 0) g_rowptr[NN] = E;
}

__global__ void fill_kernel(const int* __restrict__ src,
                            const int* __restrict__ dst, int E) {
    int e = blockIdx.x * blockDim.x + threadIdx.x;
    if (e >= E) return;
    int d = dst[e];
    int p = g_rowptr[d] + atomicAdd(&g_cur[d], 1);
    g_col[p] = src[e];
}

// ---------------- gather: agg16[d] = fp16((1+eps)h[d] + sum h[nb]) ------------
__device__ __forceinline__ void addh4(float* acc, const __half* base,
                                      int node, int lane, float w) {
    uint2 v = ((const uint2*)(base + (size_t)node * DD))[lane];
    float2 f0 = __half22float2(*(const __half2*)&v.x);
    float2 f1 = __half22float2(*(const __half2*)&v.y);
    acc[0] += w * f0.x; acc[1] += w * f0.y;
    acc[2] += w * f1.x; acc[3] += w * f1.y;
}

__global__ void gather_kernel(const float* __restrict__ xf,
                              const float* __restrict__ eps, int l, int useH,
                              int Nn) {
    long long tid = (long long)blockIdx.x * blockDim.x + threadIdx.x;
    int node = (int)(tid >> 5);
    if (node >= Nn) return;
    int lane = (int)(tid & 31);
    float e1 = 1.0f + eps[l];
    float acc[4] = {0.0f, 0.0f, 0.0f, 0.0f};

    int s = g_rowptr[node], t = g_rowptr[node + 1];
    if (useH) {
        addh4(acc, g_hh16, node, lane, e1);
        for (int i = s; i < t; i++) addh4(acc, g_hh16, g_col[i], lane, 1.0f);
    } else {
        const float4* xv = (const float4*)xf;
        float4 a = xv[(size_t)node * 32 + lane];
        acc[0] = e1 * a.x; acc[1] = e1 * a.y;
        acc[2] = e1 * a.z; acc[3] = e1 * a.w;
        for (int i = s; i < t; i++) {
            float4 v = xv[(size_t)g_col[i] * 32 + lane];
            acc[0] += v.x; acc[1] += v.y; acc[2] += v.z; acc[3] += v.w;
        }
    }
    __half2 h0 = __floats2half2_rn(acc[0], acc[1]);
    __half2 h1 = __floats2half2_rn(acc[2], acc[3]);
    uint2 o = {*(uint32_t*)&h0, *(uint32_t*)&h1};
    ((uint2*)(g_agg16 + (size_t)node * DD))[lane] = o;
}

// ---------------- fused MLP: h = act2(relu(A@W1+b1)@W2+b2) --------------------
// One CTA = 128 rows. A[128,128]fp16, W1t[256][128], W2t[128][256] fp16.
// SMEM: W1 (stride 272, 69632B) | W2 (stride 528, 67584B) | AY (67584B):
//   A tile stride 272 during GEMM1, then y[128x256] stride 528.
#define CP16(smb, g) \
    asm volatile("cp.async.cg.shared.global [%0], [%1], 16;" :: "r"(smb), "l"(g))
#define W1O 0
#define W2O 69632
#define AYO 137216
#define SMEM_TOT 204800

__global__ __launch_bounds__(256) void mlp_fused(
    const __half* __restrict__ A, const __half* __restrict__ W1t,
    const float* __restrict__ b1, const __half* __restrict__ W2t,
    const float* __restrict__ b2, __half* __restrict__ H16,
    float* __restrict__ H32, int doRelu2, int write32) {
    extern __shared__ char sm[];
    uint32_t sb  = (uint32_t)__cvta_generic_to_shared(sm);
    uint32_t w1b = sb + W1O, w2b = sb + W2O, ayb = sb + AYO;

    int tid  = threadIdx.x;
    int lane = tid & 31;
    int wid  = tid >> 5;
    int wm   = wid & 1;                      // 2 warp rows of 64
    int wn   = wid >> 1;                     // 4 warp cols
    int row0 = blockIdx.x * 128;

    // ---- group 0: A tile + W1 ----
    for (int i = tid; i < 2048; i += 256) {  // A: 128 rows x 16 chunks
        int r = i >> 4, c = i & 15;
        CP16(ayb + r * 272 + c * 16, A + (size_t)(row0 + r) * 128 + c * 8);
    }
    for (int i = tid; i < 4096; i += 256) {  // W1: 256 rows x 16 chunks
        int r = i >> 4, c = i & 15;
        CP16(w1b + r * 272 + c * 16, W1t + (size_t)r * 128 + c * 8);
    }
    asm volatile("cp.async.commit_group;");
    // ---- group 1: W2 ----
    for (int i = tid; i < 4096; i += 256) {  // W2: 128 rows x 32 chunks
        int r = i >> 5, c = i & 31;
        CP16(w2b + r * 528 + c * 16, W2t + (size_t)r * 256 + c * 8);
    }
    asm volatile("cp.async.commit_group;");
    asm volatile("cp.async.wait_group 1;");
    __syncthreads();

    int r8  = lane & 7;
    int sel = lane >> 3;
    int ll  = lane & 15;
    int bs  = ll >> 3;
    int br  = ll & 7;
    int g   = lane >> 2;
    int tg  = lane & 3;

    // ================= GEMM1: y[128,256] = A[128,128] @ W1 ===================
    float acc[4][8][4];
#pragma unroll
    for (int mt = 0; mt < 4; mt++)
#pragma unroll
        for (int nt = 0; nt < 8; nt++)
#pragma unroll
            for (int j = 0; j < 4; j++) acc[mt][nt][j] = 0.0f;

#pragma unroll
    for (int k0 = 0; k0 < 4; k0++) {
#pragma unroll
        for (int ks = 0; ks < 2; ks++) {
            uint32_t a[4][4], b[8][2];
            int kb = k0 * 64 + ks * 32;
#pragma unroll
            for (int mt = 0; mt < 4; mt++) {
                int m = wm * 64 + mt * 16 + (sel & 1) * 8 + r8;
                uint32_t ad = ayb + m * 272 + kb + ((sel >> 1) & 1) * 16;
                asm volatile(
                    "ldmatrix.sync.aligned.m8n8.x4.shared.b16 {%0,%1,%2,%3}, [%4];"
                    : "=r"(a[mt][0]), "=r"(a[mt][1]), "=r"(a[mt][2]), "=r"(a[mt][3])
                    : "r"(ad));
            }
#pragma unroll
            for (int nt = 0; nt < 8; nt++) {
                int n = wn * 64 + nt * 8 + br;
                uint32_t ad = w1b + n * 272 + kb + bs * 16;
                asm volatile(
                    "ldmatrix.sync.aligned.m8n8.x2.shared.b16 {%0,%1}, [%2];"
                    : "=r"(b[nt][0]), "=r"(b[nt][1]) : "r"(ad));
            }
#pragma unroll
            for (int mt = 0; mt < 4; mt++)
#pragma unroll
                for (int nt = 0; nt < 8; nt++) {
                    asm volatile(
                        "mma.sync.aligned.m16n8k16.row.col.f32.f16.f16.f32 "
                        "{%0,%1,%2,%3}, {%4,%5,%6,%7}, {%8,%9}, {%0,%1,%2,%3};"
                        : "+f"(acc[mt][nt][0]), "+f"(acc[mt][nt][1]),
                          "+f"(acc[mt][nt][2]), "+f"(acc[mt][nt][3])
                        : "r"(a[mt][0]), "r"(a[mt][1]), "r"(a[mt][2]), "r"(a[mt][3]),
                          "r"(b[nt][0]), "r"(b[nt][1]));
                }
        }
    }
    __syncthreads();   // A reads done; AY becomes y

    // ---- bias + relu + fp16, store y to SMEM (stride 528) ----
#pragma unroll
    for (int mt = 0; mt < 4; mt++) {
#pragma unroll
        for (int nt = 0; nt < 8; nt++) {
            int col = wn * 64 + nt * 8 + tg * 2;
            float2 bv = *(const float2*)(b1 + col);
            int r0 = wm * 64 + mt * 16 + g;
            float f0 = fmaxf(acc[mt][nt][0] + bv.x, 0.0f);
            float f1 = fmaxf(acc[mt][nt][1] + bv.y, 0.0f);
            float f2 = fmaxf(acc[mt][nt][2] + bv.x, 0.0f);
            float f3 = fmaxf(acc[mt][nt][3] + bv.y, 0.0f);
            __half2 p0 = __floats2half2_rn(f0, f1);
            __half2 p1 = __floats2half2_rn(f2, f3);
            *(__half2*)(sm + AYO + r0 * 528 + col * 2)       = p0;
            *(__half2*)(sm + AYO + (r0 + 8) * 528 + col * 2) = p1;
        }
    }
    asm volatile("cp.async.wait_group 0;");   // W2 resident
    __syncthreads();

    // ================= GEMM2: h[128,128] = y[128,256] @ W2 ===================
    float acc2[4][4][4];
#pragma unroll
    for (int mt = 0; mt < 4; mt++)
#pragma unroll
        for (int nt = 0; nt < 4; nt++)
#pragma unroll
            for (int j = 0; j < 4; j++) acc2[mt][nt][j] = 0.0f;

#pragma unroll
    for (int k0 = 0; k0 < 8; k0++) {
#pragma unroll
        for (int ks = 0; ks < 2; ks++) {
            uint32_t a[4][4], b[4][2];
            int kb = k0 * 64 + ks * 32;
#pragma unroll
            for (int mt = 0; mt < 4; mt++) {
                int m = wm * 64 + mt * 16 + (sel & 1) * 8 + r8;
                uint32_t ad = ayb + m * 528 + kb + ((sel >> 1) & 1) * 16;
                asm volatile(
                    "ldmatrix.sync.aligned.m8n8.x4.shared.b16 {%0,%1,%2,%3}, [%4];"
                    : "=r"(a[mt][0]), "=r"(a[mt][1]), "=r"(a[mt][2]), "=r"(a[mt][3])
                    : "r"(ad));
            }
#pragma unroll
            for (int nt = 0; nt < 4; nt++) {
                int n = wn * 32 + nt * 8 + br;
                uint32_t ad = w2b + n * 528 + kb + bs * 16;
                asm volatile(
                    "ldmatrix.sync.aligned.m8n8.x2.shared.b16 {%0,%1}, [%2];"
                    : "=r"(b[nt][0]), "=r"(b[nt][1]) : "r"(ad));
            }
#pragma unroll
            for (int mt = 0; mt < 4; mt++)
#pragma unroll
                for (int nt = 0; nt < 4; nt++) {
                    asm volatile(
                        "mma.sync.aligned.m16n8k16.row.col.f32.f16.f16.f32 "
                        "{%0,%1,%2,%3}, {%4,%5,%6,%7}, {%8,%9}, {%0,%1,%2,%3};"
                        : "+f"(acc2[mt][nt][0]), "+f"(acc2[mt][nt][1]),
                          "+f"(acc2[mt][nt][2]), "+f"(acc2[mt][nt][3])
                        : "r"(a[mt][0]), "r"(a[mt][1]), "r"(a[mt][2]), "r"(a[mt][3]),
                          "r"(b[nt][0]), "r"(b[nt][1]));
                }
        }
    }

    // ---- epilogue to global ----
#pragma unroll
    for (int mt = 0; mt < 4; mt++) {
#pragma unroll
        for (int nt = 0; nt < 4; nt++) {
            int col = wn * 32 + nt * 8 + tg * 2;
            float2 bv = *(const float2*)(b2 + col);
            int r0 = row0 + wm * 64 + mt * 16 + g;
            float2 o0, o1;
            o0.x = acc2[mt][nt][0] + bv.x;
            o0.y = acc2[mt][nt][1] + bv.y;
            o1.x = acc2[mt][nt][2] + bv.x;
            o1.y = acc2[mt][nt][3] + bv.y;
            if (doRelu2) {
                o0.x = fmaxf(o0.x, 0.0f); o0.y = fmaxf(o0.y, 0.0f);
                o1.x = fmaxf(o1.x, 0.0f); o1.y = fmaxf(o1.y, 0.0f);
            }
            __half2 p0 = __floats2half2_rn(o0.x, o0.y);
            __half2 p1 = __floats2half2_rn(o1.x, o1.y);
            *(__half2*)(H16 + (size_t)r0 * DD + col)       = p0;
            *(__half2*)(H16 + (size_t)(r0 + 8) * DD + col) = p1;
            if (write32) {
                *(float2*)(H32 + (size_t)r0 * DD + col)       = o0;
                *(float2*)(H32 + (size_t)(r0 + 8) * DD + col) = o1;
            }
        }
    }
}

// ---------------- pooling -----------------------------------------------------
__device__ __forceinline__ void red_add_v4(float* p, float4 v) {
    asm volatile("red.global.add.v4.f32 [%0], {%1,%2,%3,%4};"
                 :: "l"(p), "f"(v.x), "f"(v.y), "f"(v.z), "f"(v.w)
                 : "memory");
}

__global__ void prefix_kernel(const int* __restrict__ ns, int G) {
    if (blockIdx.x == 0 && threadIdx.x == 0) {
        int a = 0;
        for (int g = 0; g < G; ++g) { g_off[g] = a; a += ns[g]; }
    }
}

__global__ void zero_kernel(float* __restrict__ out, int n_out) {
    int i = blockIdx.x * blockDim.x + threadIdx.x;
    if (i < n_out) out[i] = 0.0f;
    if (i < TSG) g_cnt[i] = 0.0f;
}

__global__ void pool_kernel(const int* __restrict__ batch,
                            const int* __restrict__ sgb,
                            float* __restrict__ sums, int Nnodes) {
    long long tid = (long long)blockIdx.x * blockDim.x + threadIdx.x;
    int node = (int)(tid >> 5);
    if (node >= Nnodes) return;
    int lane = (int)(tid & 31);
    int sg = g_off[batch[node]] + sgb[node];
    float4 v = ((const float4*)g_h)[(size_t)node * 32 + lane];
    red_add_v4(sums + (size_t)sg * DD + lane * 4, v);
    if (lane == 0) atomicAdd(&g_cnt[sg], 1.0f);
}

__global__ void div_kernel(float* __restrict__ sums, int total) {
    int i = blockIdx.x * blockDim.x + threadIdx.x;
    if (i >= total) return;
    sums[i] /= fmaxf(g_cnt[i / DD], 1.0f);
}

// ---------------- launch ------------------------------------------------------
extern "C" void kernel_launch(void* const* d_in, const int* in_sizes, int n_in,
                              void* d_out, int out_size) {
    const float* x     = (const float*)d_in[0];
    const int*   edge  = (const int*)d_in[1];
    const int*   batch = (const int*)d_in[2];
    const int*   sgb   = (const int*)d_in[3];
    const int*   nsg   = (const int*)d_in[4];
    const float* W1  = (const float*)d_in[5];
    const float* b1  = (const float*)d_in[6];
    const float* W2  = (const float*)d_in[7];
    const float* b2  = (const float*)d_in[8];
    const float* eps = (const float*)d_in[9];
    float* out = (float*)d_out;

    int N = in_sizes[0] / DD;
    int E = in_sizes[1] / 2;
    int G = in_sizes[4];
    const int* src = edge;
    const int* dst = edge + E;

    void *ph, *ph16, *pa, *pw, *pc;
    cudaGetSymbolAddress(&ph, g_h);
    cudaGetSymbolAddress(&ph16, g_hh16);
    cudaGetSymbolAddress(&pa, g_agg16);
    cudaGetSymbolAddress(&pw, g_w16t);
    cudaGetSymbolAddress(&pc, g_cur);
    float*  h     = (float*)ph;
    __half* h16   = (__half*)ph16;
    __half* agg16 = (__half*)pa;
    __half* w16t  = (__half*)pw;

    static bool attrSet = false;
    if (!attrSet) {
        cudaFuncSetAttribute(mlp_fused,
                             cudaFuncAttributeMaxDynamicSharedMemorySize, SMEM_TOT);
        attrSet = true;
    }

    // one-time per launch: weights + CSR
    convw_kernel<<<(LL * 65536 + 255) / 256, 256>>>(W1, W2);
    prefix_kernel<<<1, 32>>>(nsg, G);
    cudaMemsetAsync(pc, 0, (size_t)NN * 4, 0);
    hist_kernel<<<(E + 255) / 256, 256>>>(dst, E);
    scan1_kernel<<<NCHUNK, 256>>>();
    scan2_kernel<<<1, 512>>>();
    scan3_kernel<<<(NN + 255) / 256, 256>>>(E);
    cudaMemsetAsync(pc, 0, (size_t)NN * 4, 0);
    fill_kernel<<<(E + 255) / 256, 256>>>(src, dst, E);

    for (int l = 0; l < LL; l++) {
        gather_kernel<<<(int)(((long long)N * 32 + 255) / 256), 256>>>(
            x, eps, l, (l > 0) ? 1 : 0, N);
        mlp_fused<<<N / 128, 256, SMEM_TOT>>>(
            agg16, w16t + (size_t)l * 65536, b1 + (size_t)l * 256,
            w16t + (size_t)l * 65536 + 32768, b2 + (size_t)l * 128,
            h16, h, (l < LL - 1) ? 1 : 0, (l == LL - 1) ? 1 : 0);
    }

    zero_kernel<<<(out_size + 255) / 256, 256>>>(out, out_size);
    pool_kernel<<<(int)(((long long)N * 32 + 255) / 256), 256>>>(batch, sgb, out, N);
    div_kernel<<<(out_size + 255) / 256, 256>>>(out, out_size);
}

// round 7
// speedup vs baseline: 6.2994x; 1.1080x over previous
#include <cuda_runtime.h>
#include <cuda_fp16.h>
#include <cstdint>
#include <cstddef>

#define NN  102400
#define EE  819200
#define DD  128
#define LL  5
#define TSG 1024
#define NCHUNK 400          // NN / 256

// ---------------- scratch (static device globals) ----------------------------
__device__ __half g_hh16[(size_t)NN * DD];       // fp16 activations (gather in)
__device__ __half g_agg16[(size_t)NN * DD];      // MLP input
__device__ __half g_w16t[(size_t)LL * 65536];    // transposed fp16 weights
__device__ int    g_rowptr[NN + 1];
__device__ int    g_cur[NN];
__device__ int    g_bsum[NCHUNK];
__device__ int    g_col[EE];
__device__ float  g_cnt[TSG];
__device__ int    g_off[64];

// ---------------- weight convert + transpose ---------------------------------
// per layer l: [0,32768): W1^T [n=256][k=128]; [32768,65536): W2^T [n=128][k=256]
__global__ void convw_kernel(const float* __restrict__ W1,
                             const float* __restrict__ W2) {
    int i = blockIdx.x * blockDim.x + threadIdx.x;
    if (i >= LL * 65536) return;
    int l = i >> 16, r = i & 65535;
    float v;
    if (r < 32768) {
        int n = r >> 7, k = r & 127;
        v = W1[(size_t)l * 32768 + k * 256 + n];
    } else {
        int r2 = r - 32768;
        int n = r2 >> 8, k = r2 & 255;
        v = W2[(size_t)l * 32768 + k * 128 + n];
    }
    g_w16t[i] = __float2half_rn(v);
}

// ---------------- CSR build ---------------------------------------------------
__global__ void hist_kernel(const int* __restrict__ dst, int E) {
    int e = blockIdx.x * blockDim.x + threadIdx.x;
    if (e < E) atomicAdd(&g_cur[dst[e]], 1);
}

__global__ void scan1_kernel() {
    __shared__ int s[256];
    int t = threadIdx.x, i = blockIdx.x * 256 + t;
    int v = g_cur[i];
    s[t] = v;
    __syncthreads();
#pragma unroll
    for (int o = 1; o < 256; o <<= 1) {
        int u = (t >= o) ? s[t - o] : 0;
        __syncthreads();
        s[t] += u;
        __syncthreads();
    }
    g_rowptr[i] = s[t] - v;
    if (t == 255) g_bsum[blockIdx.x] = s[255];
}

__global__ void scan2_kernel() {
    __shared__ int s[512];
    int t = threadIdx.x;
    int v = (t < NCHUNK) ? g_bsum[t] : 0;
    s[t] = v;
    __syncthreads();
#pragma unroll
    for (int o = 1; o < 512; o <<= 1) {
        int u = (t >= o) ? s[t - o] : 0;
        __syncthreads();
        s[t] += u;
        __syncthreads();
    }
    if (t < NCHUNK) g_bsum[t] = s[t] - v;
}

__global__ void scan3_kernel(int E) {
    int i = blockIdx.x * blockDim.x + threadIdx.x;
    if (i < NN) g_rowptr[i] += g_bsum[i >> 8];
    if (i == 0) g_rowptr[NN] = E;
}

__global__ void fill_kernel(const int* __restrict__ src,
                            const int* __restrict__ dst, int E) {
    int e = blockIdx.x * blockDim.x + threadIdx.x;
    if (e >= E) return;
    int d = dst[e];
    int p = g_rowptr[d] + atomicAdd(&g_cur[d], 1);
    g_col[p] = src[e];
}

// ---------------- gather: agg16[d] = fp16((1+eps)h[d] + sum h[nb]) ------------
__device__ __forceinline__ void addh4(float* acc, const __half* base,
                                      int node, int lane, float w) {
    uint2 v = ((const uint2*)(base + (size_t)node * DD))[lane];
    float2 f0 = __half22float2(*(const __half2*)&v.x);
    float2 f1 = __half22float2(*(const __half2*)&v.y);
    acc[0] += w * f0.x; acc[1] += w * f0.y;
    acc[2] += w * f1.x; acc[3] += w * f1.y;
}

__global__ void gather_kernel(const float* __restrict__ xf,
                              const float* __restrict__ eps, int l, int useH,
                              int Nn) {
    long long tid = (long long)blockIdx.x * blockDim.x + threadIdx.x;
    int node = (int)(tid >> 5);
    if (node >= Nn) return;
    int lane = (int)(tid & 31);
    float e1 = 1.0f + eps[l];
    float acc[4] = {0.0f, 0.0f, 0.0f, 0.0f};

    int s = g_rowptr[node], t = g_rowptr[node + 1];
    if (useH) {
        addh4(acc, g_hh16, node, lane, e1);
        for (int i = s; i < t; i++) addh4(acc, g_hh16, g_col[i], lane, 1.0f);
    } else {
        const float4* xv = (const float4*)xf;
        float4 a = xv[(size_t)node * 32 + lane];
        acc[0] = e1 * a.x; acc[1] = e1 * a.y;
        acc[2] = e1 * a.z; acc[3] = e1 * a.w;
        for (int i = s; i < t; i++) {
            float4 v = xv[(size_t)g_col[i] * 32 + lane];
            acc[0] += v.x; acc[1] += v.y; acc[2] += v.z; acc[3] += v.w;
        }
    }
    __half2 h0 = __floats2half2_rn(acc[0], acc[1]);
    __half2 h1 = __floats2half2_rn(acc[2], acc[3]);
    uint2 o = {*(uint32_t*)&h0, *(uint32_t*)&h1};
    ((uint2*)(g_agg16 + (size_t)node * DD))[lane] = o;
}

// ---------------- persistent fused MLP ----------------------------------------
// grid = 148 persistent CTAs; each strides tiles of 128 rows.
// SMEM: W1 (stride 272, 69632B) | W2 (stride 528, 67584B) | AY (67584B)
#define CP16(smb, g) \
    asm volatile("cp.async.cg.shared.global [%0], [%1], 16;" :: "r"(smb), "l"(g))
#define W1O 0
#define W2O 69632
#define AYO 137216
#define SMEM_TOT 204800

__device__ __forceinline__ void red_add_v2(float* p, float2 v) {
    asm volatile("red.global.add.v2.f32 [%0], {%1,%2};"
                 :: "l"(p), "f"(v.x), "f"(v.y) : "memory");
}

__global__ __launch_bounds__(256) void mlp_fused(
    const __half* __restrict__ A, const __half* __restrict__ W1t,
    const float* __restrict__ b1, const __half* __restrict__ W2t,
    const float* __restrict__ b2, __half* __restrict__ H16,
    const int* __restrict__ batch, const int* __restrict__ sgb,
    float* __restrict__ out, int ntiles, int doRelu2, int doPool) {
    extern __shared__ char sm[];
    uint32_t sb  = (uint32_t)__cvta_generic_to_shared(sm);
    uint32_t w1b = sb + W1O, w2b = sb + W2O, ayb = sb + AYO;

    int tid  = threadIdx.x;
    int lane = tid & 31;
    int wid  = tid >> 5;
    int wm   = wid & 1;                      // 2 warp rows of 64
    int wn   = wid >> 1;                     // 4 warp cols
    int stride = gridDim.x;

    // ---- group 0: W1 + A(tile0); group 1: W2 ----
    for (int i = tid; i < 4096; i += 256) {  // W1: 256 rows x 16 chunks
        int r = i >> 4, c = i & 15;
        CP16(w1b + r * 272 + c * 16, W1t + (size_t)r * 128 + c * 8);
    }
    {
        int row0 = blockIdx.x * 128;
        for (int i = tid; i < 2048; i += 256) {  // A: 128 rows x 16 chunks
            int r = i >> 4, c = i & 15;
            CP16(ayb + r * 272 + c * 16, A + (size_t)(row0 + r) * 128 + c * 8);
        }
    }
    asm volatile("cp.async.commit_group;");
    for (int i = tid; i < 4096; i += 256) {  // W2: 128 rows x 32 chunks
        int r = i >> 5, c = i & 31;
        CP16(w2b + r * 528 + c * 16, W2t + (size_t)r * 256 + c * 8);
    }
    asm volatile("cp.async.commit_group;");
    asm volatile("cp.async.wait_group 1;");
    __syncthreads();

    int r8  = lane & 7;
    int sel = lane >> 3;
    int ll  = lane & 15;
    int bs  = ll >> 3;
    int br  = ll & 7;
    int g   = lane >> 2;
    int tg  = lane & 3;

    bool firstIter = true;
    for (int tile = blockIdx.x; tile < ntiles; tile += stride) {
        int row0 = tile * 128;
        int nextTile = tile + stride;
        bool hasNext = nextTile < ntiles;

        // ---- prefetch next A tile into registers (consumed post-GEMM2) ----
        uint4 pf[8];
        if (hasNext) {
            const uint4* Ag = (const uint4*)(A + (size_t)nextTile * 128 * 128);
#pragma unroll
            for (int j = 0; j < 8; j++) pf[j] = Ag[tid + 256 * j];
        }

        // ============ GEMM1: y[128,256] = A[128,128] @ W1 ============
        float acc[4][8][4];
#pragma unroll
        for (int mt = 0; mt < 4; mt++)
#pragma unroll
            for (int nt = 0; nt < 8; nt++)
#pragma unroll
                for (int j = 0; j < 4; j++) acc[mt][nt][j] = 0.0f;

#pragma unroll
        for (int k0 = 0; k0 < 4; k0++) {
#pragma unroll
            for (int ks = 0; ks < 2; ks++) {
                uint32_t a[4][4], b[8][2];
                int kb = k0 * 64 + ks * 32;
#pragma unroll
                for (int mt = 0; mt < 4; mt++) {
                    int m = wm * 64 + mt * 16 + (sel & 1) * 8 + r8;
                    uint32_t ad = ayb + m * 272 + kb + ((sel >> 1) & 1) * 16;
                    asm volatile(
                        "ldmatrix.sync.aligned.m8n8.x4.shared.b16 {%0,%1,%2,%3}, [%4];"
                        : "=r"(a[mt][0]), "=r"(a[mt][1]), "=r"(a[mt][2]), "=r"(a[mt][3])
                        : "r"(ad));
                }
#pragma unroll
                for (int nt = 0; nt < 8; nt++) {
                    int n = wn * 64 + nt * 8 + br;
                    uint32_t ad = w1b + n * 272 + kb + bs * 16;
                    asm volatile(
                        "ldmatrix.sync.aligned.m8n8.x2.shared.b16 {%0,%1}, [%2];"
                        : "=r"(b[nt][0]), "=r"(b[nt][1]) : "r"(ad));
                }
#pragma unroll
                for (int mt = 0; mt < 4; mt++)
#pragma unroll
                    for (int nt = 0; nt < 8; nt++) {
                        asm volatile(
                            "mma.sync.aligned.m16n8k16.row.col.f32.f16.f16.f32 "
                            "{%0,%1,%2,%3}, {%4,%5,%6,%7}, {%8,%9}, {%0,%1,%2,%3};"
                            : "+f"(acc[mt][nt][0]), "+f"(acc[mt][nt][1]),
                              "+f"(acc[mt][nt][2]), "+f"(acc[mt][nt][3])
                            : "r"(a[mt][0]), "r"(a[mt][1]), "r"(a[mt][2]), "r"(a[mt][3]),
                              "r"(b[nt][0]), "r"(b[nt][1]));
                    }
            }
        }
        __syncthreads();   // A reads done; AY becomes y

        // ---- bias + relu + fp16, store y to SMEM (stride 528) ----
#pragma unroll
        for (int mt = 0; mt < 4; mt++) {
#pragma unroll
            for (int nt = 0; nt < 8; nt++) {
                int col = wn * 64 + nt * 8 + tg * 2;
                float2 bv = *(const float2*)(b1 + col);
                int r0 = wm * 64 + mt * 16 + g;
                float f0 = fmaxf(acc[mt][nt][0] + bv.x, 0.0f);
                float f1 = fmaxf(acc[mt][nt][1] + bv.y, 0.0f);
                float f2 = fmaxf(acc[mt][nt][2] + bv.x, 0.0f);
                float f3 = fmaxf(acc[mt][nt][3] + bv.y, 0.0f);
                __half2 p0 = __floats2half2_rn(f0, f1);
                __half2 p1 = __floats2half2_rn(f2, f3);
                *(__half2*)(sm + AYO + r0 * 528 + col * 2)       = p0;
                *(__half2*)(sm + AYO + (r0 + 8) * 528 + col * 2) = p1;
            }
        }
        if (firstIter) {
            asm volatile("cp.async.wait_group 0;");   // W2 resident
            firstIter = false;
        }
        __syncthreads();

        // ============ GEMM2: h[128,128] = y[128,256] @ W2 ============
        float acc2[4][4][4];
#pragma unroll
        for (int mt = 0; mt < 4; mt++)
#pragma unroll
            for (int nt = 0; nt < 4; nt++)
#pragma unroll
                for (int j = 0; j < 4; j++) acc2[mt][nt][j] = 0.0f;

#pragma unroll
        for (int k0 = 0; k0 < 8; k0++) {
#pragma unroll
            for (int ks = 0; ks < 2; ks++) {
                uint32_t a[4][4], b[4][2];
                int kb = k0 * 64 + ks * 32;
#pragma unroll
                for (int mt = 0; mt < 4; mt++) {
                    int m = wm * 64 + mt * 16 + (sel & 1) * 8 + r8;
                    uint32_t ad = ayb + m * 528 + kb + ((sel >> 1) & 1) * 16;
                    asm volatile(
                        "ldmatrix.sync.aligned.m8n8.x4.shared.b16 {%0,%1,%2,%3}, [%4];"
                        : "=r"(a[mt][0]), "=r"(a[mt][1]), "=r"(a[mt][2]), "=r"(a[mt][3])
                        : "r"(ad));
                }
#pragma unroll
                for (int nt = 0; nt < 4; nt++) {
                    int n = wn * 32 + nt * 8 + br;
                    uint32_t ad = w2b + n * 528 + kb + bs * 16;
                    asm volatile(
                        "ldmatrix.sync.aligned.m8n8.x2.shared.b16 {%0,%1}, [%2];"
                        : "=r"(b[nt][0]), "=r"(b[nt][1]) : "r"(ad));
                }
#pragma unroll
                for (int mt = 0; mt < 4; mt++)
#pragma unroll
                    for (int nt = 0; nt < 4; nt++) {
                        asm volatile(
                            "mma.sync.aligned.m16n8k16.row.col.f32.f16.f16.f32 "
                            "{%0,%1,%2,%3}, {%4,%5,%6,%7}, {%8,%9}, {%0,%1,%2,%3};"
                            : "+f"(acc2[mt][nt][0]), "+f"(acc2[mt][nt][1]),
                              "+f"(acc2[mt][nt][2]), "+f"(acc2[mt][nt][3])
                            : "r"(a[mt][0]), "r"(a[mt][1]), "r"(a[mt][2]), "r"(a[mt][3]),
                              "r"(b[nt][0]), "r"(b[nt][1]));
                    }
            }
        }
        __syncthreads();   // y reads done; AY free

        // ---- write next A tile from registers ----
        if (hasNext) {
#pragma unroll
            for (int j = 0; j < 8; j++) {
                int i2 = tid + 256 * j;
                int r = i2 >> 4, c = i2 & 15;
                *(uint4*)(sm + AYO + r * 272 + c * 16) = pf[j];
            }
        }

        // ---- epilogue: global h16 or fused pool ----
        if (doPool) {
#pragma unroll
            for (int mt = 0; mt < 4; mt++) {
                int ra = row0 + wm * 64 + mt * 16 + g;
                int sgA = g_off[batch[ra]] + sgb[ra];
                int sgB = g_off[batch[ra + 8]] + sgb[ra + 8];
#pragma unroll
                for (int nt = 0; nt < 4; nt++) {
                    int col = wn * 32 + nt * 8 + tg * 2;
                    float2 bv = *(const float2*)(b2 + col);
                    float2 o0 = {acc2[mt][nt][0] + bv.x, acc2[mt][nt][1] + bv.y};
                    float2 o1 = {acc2[mt][nt][2] + bv.x, acc2[mt][nt][3] + bv.y};
                    red_add_v2(out + (size_t)sgA * DD + col, o0);
                    red_add_v2(out + (size_t)sgB * DD + col, o1);
                }
            }
        } else {
#pragma unroll
            for (int mt = 0; mt < 4; mt++) {
#pragma unroll
                for (int nt = 0; nt < 4; nt++) {
                    int col = wn * 32 + nt * 8 + tg * 2;
                    float2 bv = *(const float2*)(b2 + col);
                    int r0 = row0 + wm * 64 + mt * 16 + g;
                    float2 o0, o1;
                    o0.x = acc2[mt][nt][0] + bv.x;
                    o0.y = acc2[mt][nt][1] + bv.y;
                    o1.x = acc2[mt][nt][2] + bv.x;
                    o1.y = acc2[mt][nt][3] + bv.y;
                    if (doRelu2) {
                        o0.x = fmaxf(o0.x, 0.0f); o0.y = fmaxf(o0.y, 0.0f);
                        o1.x = fmaxf(o1.x, 0.0f); o1.y = fmaxf(o1.y, 0.0f);
                    }
                    __half2 p0 = __floats2half2_rn(o0.x, o0.y);
                    __half2 p1 = __floats2half2_rn(o1.x, o1.y);
                    *(__half2*)(H16 + (size_t)r0 * DD + col)       = p0;
                    *(__half2*)(H16 + (size_t)(r0 + 8) * DD + col) = p1;
                }
            }
        }
        __syncthreads();   // STS of next A visible before next GEMM1
    }
}

// ---------------- pooling helpers ---------------------------------------------
__global__ void prefix_kernel(const int* __restrict__ ns, int G) {
    if (blockIdx.x == 0 && threadIdx.x == 0) {
        int a = 0;
        for (int g = 0; g < G; ++g) { g_off[g] = a; a += ns[g]; }
    }
}

__global__ void zero_kernel(float* __restrict__ out, int n_out) {
    int i = blockIdx.x * blockDim.x + threadIdx.x;
    if (i < n_out) out[i] = 0.0f;
    if (i < TSG) g_cnt[i] = 0.0f;
}

__global__ void count_kernel(const int* __restrict__ batch,
                             const int* __restrict__ sgb, int Nn) {
    int i = blockIdx.x * blockDim.x + threadIdx.x;
    if (i < Nn) atomicAdd(&g_cnt[g_off[batch[i]] + sgb[i]], 1.0f);
}

__global__ void div_kernel(float* __restrict__ sums, int total) {
    int i = blockIdx.x * blockDim.x + threadIdx.x;
    if (i >= total) return;
    sums[i] /= fmaxf(g_cnt[i / DD], 1.0f);
}

// ---------------- launch ------------------------------------------------------
extern "C" void kernel_launch(void* const* d_in, const int* in_sizes, int n_in,
                              void* d_out, int out_size) {
    const float* x     = (const float*)d_in[0];
    const int*   edge  = (const int*)d_in[1];
    const int*   batch = (const int*)d_in[2];
    const int*   sgb   = (const int*)d_in[3];
    const int*   nsg   = (const int*)d_in[4];
    const float* W1  = (const float*)d_in[5];
    const float* b1  = (const float*)d_in[6];
    const float* W2  = (const float*)d_in[7];
    const float* b2  = (const float*)d_in[8];
    const float* eps = (const float*)d_in[9];
    float* out = (float*)d_out;

    int N = in_sizes[0] / DD;
    int E = in_sizes[1] / 2;
    int G = in_sizes[4];
    const int* src = edge;
    const int* dst = edge + E;

    void *ph16, *pa, *pw, *pc;
    cudaGetSymbolAddress(&ph16, g_hh16);
    cudaGetSymbolAddress(&pa, g_agg16);
    cudaGetSymbolAddress(&pw, g_w16t);
    cudaGetSymbolAddress(&pc, g_cur);
    __half* h16   = (__half*)ph16;
    __half* agg16 = (__half*)pa;
    __half* w16t  = (__half*)pw;

    static bool attrSet = false;
    if (!attrSet) {
        cudaFuncSetAttribute(mlp_fused,
                             cudaFuncAttributeMaxDynamicSharedMemorySize, SMEM_TOT);
        attrSet = true;
    }

    // one-time per launch: weights + CSR + pool metadata
    convw_kernel<<<(LL * 65536 + 255) / 256, 256>>>(W1, W2);
    prefix_kernel<<<1, 32>>>(nsg, G);
    cudaMemsetAsync(pc, 0, (size_t)NN * 4, 0);
    hist_kernel<<<(E + 255) / 256, 256>>>(dst, E);
    scan1_kernel<<<NCHUNK, 256>>>();
    scan2_kernel<<<1, 512>>>();
    scan3_kernel<<<(NN + 255) / 256, 256>>>(E);
    cudaMemsetAsync(pc, 0, (size_t)NN * 4, 0);
    fill_kernel<<<(E + 255) / 256, 256>>>(src, dst, E);
    zero_kernel<<<(out_size + 255) / 256, 256>>>(out, out_size);
    count_kernel<<<(N + 255) / 256, 256>>>(batch, sgb, N);

    int ntiles = N / 128;
    int grid = 148 < ntiles ? 148 : ntiles;

    for (int l = 0; l < LL; l++) {
        gather_kernel<<<(int)(((long long)N * 32 + 255) / 256), 256>>>(
            x, eps, l, (l > 0) ? 1 : 0, N);
        mlp_fused<<<grid, 256, SMEM_TOT>>>(
            agg16, w16t + (size_t)l * 65536, b1 + (size_t)l * 256,
            w16t + (size_t)l * 65536 + 32768, b2 + (size_t)l * 128,
            h16, batch, sgb, out, ntiles,
            (l < LL - 1) ? 1 : 0, (l == LL - 1) ? 1 : 0);
    }

    div_kernel<<<(out_size + 255) / 256, 256>>>(out, out_size);
}